// round 3
// baseline (speedup 1.0000x reference)
#include <cuda_runtime.h>
#include <cstdint>

typedef unsigned long long ull;

#define THREADS 512
#define OUTF 11008
#define INF 4096
#define NBLK 688                    /* OUTF/16 row-blocks, one per CTA */

#define SMEM_LUT_BYTES (512*16*8)   /* LUT replicated 16x, interleaved: 64KB */
#define SMEM_RED_BYTES (16*64*4)    /* cross-warp reduction: 4KB */
#define SMEM_TOTAL (SMEM_LUT_BYTES + SMEM_RED_BYTES)

__device__ __forceinline__ uint32_t smem_u32(const void* p) {
    uint32_t a;
    asm("{ .reg .u64 t; cvta.to.shared.u64 t, %1; cvt.u32.u64 %0, t; }"
        : "=r"(a) : "l"(p));
    return a;
}
__device__ __forceinline__ ull pack2(float lo, float hi) {
    ull r; asm("mov.b64 %0, {%1,%2};" : "=l"(r) : "f"(lo), "f"(hi)); return r;
}
__device__ __forceinline__ void fma2(ull& acc, ull a, ull b) {
    asm("fma.rn.f32x2 %0, %1, %2, %0;" : "+l"(acc) : "l"(a), "l"(b));
}
__device__ __forceinline__ float sum2(ull v) {
    float a, b; asm("mov.b64 {%0,%1}, %2;" : "=f"(a), "=f"(b) : "l"(v));
    return a + b;
}
__device__ __forceinline__ ull lds64(uint32_t addr) {
    ull v; asm("ld.shared.b64 %0, [%1];" : "=l"(v) : "r"(addr));
    return v;
}

__global__ void __launch_bounds__(THREADS, 1)
tcq_kernel(const float* __restrict__ inp,
           const int* __restrict__ trellis1,
           const int* __restrict__ trellis2,
           const float* __restrict__ tlut,
           float* __restrict__ out)
{
    extern __shared__ char smem_raw[];
    ull*   lut = (ull*)smem_raw;
    float* red = (float*)(smem_raw + SMEM_LUT_BYTES);

    const int tid  = threadIdx.x;
    const int lane = tid & 31;
    const int warp = tid >> 5;
    const int mo   = blockIdx.x;
    const int ko   = tid & 255;     // trellis block within mo
    const int half = tid >> 8;      // 0: word 2tx (cols 0-7), 1: word 2tx+1 (cols 8-15)

    // ---- trellis block ko: load 32 words, pack per row: p[tx]=(w[2tx]<<16)|w[2tx+1]
    const int4* tq = (ko < 128)
        ? (const int4*)(trellis1 + (size_t)(mo * 128 + ko) * 32)
        : (const int4*)(trellis2 + (size_t)(mo * 128 + (ko - 128)) * 32);
    uint32_t p[16];
#pragma unroll
    for (int q = 0; q < 8; q++) {
        const int4 v = tq[q];
        p[2 * q + 0] = (((uint32_t)v.x & 0xFFFFu) << 16) | ((uint32_t)v.y & 0xFFFFu);
        p[2 * q + 1] = (((uint32_t)v.z & 0xFFFFu) << 16) | ((uint32_t)v.w & 0xFFFFu);
    }

    // ---- stage LUT replicated 16x interleaved: entry e, replica r at byte
    //      e*128 + r*8. Lane l reads replica l&15 -> conflict-free LDS.64
    //      for arbitrary random idx (half-warp wavefronts see distinct banks).
    {
        const ull* src = (const ull*)tlut;      // 512 float2 entries
        for (int k = tid; k < 512 * 16; k += THREADS)
            lut[k] = src[k >> 4];
    }

    // ---- x for this thread's 8 global columns [ko*16+half*8, +8), 4 batches,
    //      packed as f32x2 pairs (local pair t = step t's column pair) ----
    ull x2[4][4];
    {
        const float4* xv = (const float4*)inp;
        const int cb = ko * 4 + half * 2;       // float4 index base
#pragma unroll
        for (int b = 0; b < 4; b++) {
#pragma unroll
            for (int q = 0; q < 2; q++) {
                float4 v = xv[b * (INF / 4) + cb + q];
                x2[b][2 * q + 0] = pack2(v.x, v.y);
                x2[b][2 * q + 1] = pack2(v.z, v.w);
            }
        }
    }

    __syncthreads();

    const uint32_t lut_lane = smem_u32(smem_raw) + (uint32_t)(lane & 15) * 8u;

    // Decode: idx[s] = 9-bit window ending at nibble s of the big-endian word
    // stream (state recurrence collapses because L == 4*kv).
    // half=1 ctx for row tx is p[tx]; half=0 ctx is (w[2tx-1]<<16)|w[2tx]
    //   = funnelshift_l(p[tx], p[tx-1], 16), with p[-1] = 0.
    uint32_t pv = 0;

#pragma unroll
    for (int ph = 0; ph < 4; ph++) {            // rows ph*4 .. ph*4+3
        ull acc[4][4];                          // [row-in-phase][batch] packed f32x2
#pragma unroll
        for (int r = 0; r < 4; r++)
#pragma unroll
            for (int b = 0; b < 4; b++) acc[r][b] = 0ull;

#pragma unroll
        for (int r = 0; r < 4; r++) {
            const int tx = ph * 4 + r;
            const uint32_t ctx = half ? p[tx]
                                      : __funnelshift_l(p[tx], pv, 16);
            pv = p[tx];
#pragma unroll
            for (int t = 0; t < 4; t++) {
                const uint32_t idx = (ctx >> (12 - 4 * t)) & 0x1FFu;
                const ull w2 = lds64(lut_lane + idx * 128u);
                fma2(acc[r][0], w2, x2[0][t]);
                fma2(acc[r][1], w2, x2[1][t]);
                fma2(acc[r][2], w2, x2[2][t]);
                fma2(acc[r][3], w2, x2[3][t]);
            }
        }

        // collapse packed partials, then value-rotating warp reduction:
        // 16 sums over 32 lanes -> 1 per lane (15 shfl) + closing xor-16 add.
        float v[16];
#pragma unroll
        for (int r = 0; r < 4; r++)
#pragma unroll
            for (int b = 0; b < 4; b++) v[r * 4 + b] = sum2(acc[r][b]);

#define ROUND(S, N) { _Pragma("unroll")                                   \
        for (int i = 0; i < (N) / 2; i++) {                               \
            const bool hi = (lane & (S)) != 0;                            \
            const float snd = hi ? v[i] : v[i + (N) / 2];                 \
            const float kp  = hi ? v[i + (N) / 2] : v[i];                 \
            v[i] = kp + __shfl_xor_sync(0xffffffffu, snd, (S));           \
        } }
        ROUND(1, 16) ROUND(2, 8) ROUND(4, 4) ROUND(8, 2)
#undef ROUND
        v[0] += __shfl_xor_sync(0xffffffffu, v[0], 16);

        // lane l (l<16) holds value index bitrev4(l) = r*4+b of this phase
        const int oi = ((lane & 1) << 3) | ((lane & 2) << 1)
                     | ((lane & 4) >> 1) | ((lane & 8) >> 3);
        if (lane < 16) red[warp * 64 + ph * 16 + oi] = v[0];
    }

    __syncthreads();

    // cross-warp combine: 64 outputs (16 rows x 4 batches), 16 warps each
    if (tid < 64) {
        float s = 0.f;
#pragma unroll
        for (int w = 0; w < 16; w++) s += red[w * 64 + tid];
        const int phx = tid >> 4;         // tid = ph*16 + r*4 + b
        const int r   = (tid >> 2) & 3;
        const int b   = tid & 3;
        out[(size_t)b * OUTF + mo * 16 + phx * 4 + r] = s;
    }
}

extern "C" void kernel_launch(void* const* d_in, const int* in_sizes, int n_in,
                              void* d_out, int out_size) {
    const float* inp  = (const float*)d_in[0];
    const int*   t1   = (const int*)d_in[1];
    const int*   t2   = (const int*)d_in[2];
    const float* tlut = (const float*)d_in[3];
    float*       out  = (float*)d_out;

    cudaFuncSetAttribute(tcq_kernel,
                         cudaFuncAttributeMaxDynamicSharedMemorySize,
                         SMEM_TOTAL);
    tcq_kernel<<<NBLK, THREADS, SMEM_TOTAL>>>(inp, t1, t2, tlut, out);
}